// round 15
// baseline (speedup 1.0000x reference)
#include <cuda_runtime.h>
#include <cuda_fp16.h>
#include <math.h>

#define NN 50000
#define EE 800000
#define RR 8
#define BB 4
#define NB ((NN + 255) / 256)

// ---------------- scratch (device globals; no allocation) ----------------
__device__ __half g_xh[NN * 64];        // fp16 input x
__device__ __half g_x1h[NN * 64];       // after RGCN1 (fp16)
__device__ __half g_x2h[NN * 128];      // after GAT1 (fp16)
__device__ __half g_x3h[NN * 32];       // after RGCN2 (fp16)
__device__ __half g_h[NN * 128];        // GAT transformed features (fp16)
__device__ float  g_al[NN * 8];
__device__ __half g_z[(size_t)NN * 512];  // B-space aggregates (fp16)
__device__ int    g_cnt[NN * RR];
__device__ int    g_row_off[NN + 1];
__device__ int    g_cursor[NN];
__device__ int    g_adj[EE];            // src | (etype<<16)
__device__ int    g_pos[EE];
__device__ float  g_ev[(size_t)EE * 4];
__device__ int    g_nodescan[NN];
__device__ int    g_blocksum[NB];
__device__ int    g_blockoff[NB];
__device__ __half g_w1h[320 * 64];
__device__ __half g_wg1h[64 * 128];
__device__ __half g_w2h[640 * 32];
__device__ __half g_wg2h[32 * 64];

__device__ __forceinline__ float4 ld4(const float* p) { return __ldg((const float4*)p); }
__device__ __forceinline__ float2 ld2(const float* p) { return __ldg((const float2*)p); }

__device__ __forceinline__ float4 ldh4(const __half* p) {
    uint2 raw = __ldg((const uint2*)p);
    __half2 a = *(__half2*)&raw.x;
    __half2 b = *(__half2*)&raw.y;
    float2 fa = __half22float2(a), fb = __half22float2(b);
    return make_float4(fa.x, fa.y, fb.x, fb.y);
}
__device__ __forceinline__ float2 ldh2(const __half* p) {
    __half2 h = __ldg((const __half2*)p);
    return __half22float2(h);
}

template <int VW>
__device__ __forceinline__ void ldvh(float (&d)[VW], const __half* p) {
    if (VW == 2) {
        float2 v = ldh2(p);
        d[0] = v.x; d[1] = v.y;
    } else {
        float4 v = ldh4(p);
        d[0] = v.x; d[1] = v.y; d[2] = v.z; d[3] = v.w;
    }
}

// ---------------- tensor-core primitives ----------------
__device__ __forceinline__ void ldsm4(unsigned& r0, unsigned& r1, unsigned& r2, unsigned& r3,
                                      unsigned addr) {
    asm volatile("ldmatrix.sync.aligned.m8n8.x4.shared.b16 {%0,%1,%2,%3}, [%4];"
                 : "=r"(r0), "=r"(r1), "=r"(r2), "=r"(r3) : "r"(addr));
}
__device__ __forceinline__ void ldsm4t(unsigned& r0, unsigned& r1, unsigned& r2, unsigned& r3,
                                       unsigned addr) {
    asm volatile("ldmatrix.sync.aligned.m8n8.x4.trans.shared.b16 {%0,%1,%2,%3}, [%4];"
                 : "=r"(r0), "=r"(r1), "=r"(r2), "=r"(r3) : "r"(addr));
}
__device__ __forceinline__ void mma16816(float* d, unsigned a0, unsigned a1, unsigned a2, unsigned a3,
                                         unsigned b0, unsigned b1) {
    asm volatile("mma.sync.aligned.m16n8k16.row.col.f32.f16.f16.f32 "
                 "{%0,%1,%2,%3},{%4,%5,%6,%7},{%8,%9},{%0,%1,%2,%3};"
                 : "+f"(d[0]), "+f"(d[1]), "+f"(d[2]), "+f"(d[3])
                 : "r"(a0), "r"(a1), "r"(a2), "r"(a3), "r"(b0), "r"(b1));
}

// ---------------- CSR build ----------------
__global__ void zero_int(int* __restrict__ p, int n) {
    int i = blockIdx.x * blockDim.x + threadIdx.x;
    if (i < n) p[i] = 0;
}

__global__ void hist_kernel(const int* __restrict__ dst, const int* __restrict__ et) {
    int e = blockIdx.x * blockDim.x + threadIdx.x;
    if (e < EE) atomicAdd(&g_cnt[dst[e] * RR + et[e]], 1);
}

__global__ void scanA() {
    __shared__ int sh[256];
    int t = threadIdx.x;
    int n = blockIdx.x * 256 + t;
    int deg = 0;
    if (n < NN) {
#pragma unroll
        for (int r = 0; r < RR; r++) deg += g_cnt[n * RR + r];
    }
    int val = deg;
    sh[t] = val;
    __syncthreads();
    for (int d = 1; d < 256; d <<= 1) {
        int a = (t >= d) ? sh[t - d] : 0;
        __syncthreads();
        val += a;
        sh[t] = val;
        __syncthreads();
    }
    if (n < NN) g_nodescan[n] = val - deg;
    if (t == 255) g_blocksum[blockIdx.x] = val;
}

__global__ void scanB() {
    __shared__ int sh[256];
    int t = threadIdx.x;
    int own = (t < NB) ? g_blocksum[t] : 0;
    int val = own;
    sh[t] = val;
    __syncthreads();
    for (int d = 1; d < 256; d <<= 1) {
        int a = (t >= d) ? sh[t - d] : 0;
        __syncthreads();
        val += a;
        sh[t] = val;
        __syncthreads();
    }
    if (t < NB) g_blockoff[t] = val - own;
    if (t == NB - 1) g_row_off[NN] = val;
}

__global__ void scanC() {
    int n = blockIdx.x * 256 + threadIdx.x;
    if (n < NN) {
        int off = g_blockoff[blockIdx.x] + g_nodescan[n];
        g_row_off[n] = off;
        g_cursor[n] = off;
    }
}

__global__ void fill_kernel(const int* __restrict__ src, const int* __restrict__ dst,
                            const int* __restrict__ et) {
    int e = blockIdx.x * blockDim.x + threadIdx.x;
    if (e < EE) {
        int d = dst[e];
        int pos = atomicAdd(&g_cursor[d], 1);
        g_adj[pos] = src[e] | (et[e] << 16);
        g_pos[e] = pos;
    }
}

// ---------------- fp16 conversions (once per launch) ----------------
__global__ void x_half_kernel(const float* __restrict__ x) {
    int i = blockIdx.x * blockDim.x + threadIdx.x;
    if (i < NN * 64 / 4) {
        float4 v = ld4(x + 4 * i);
        __half2 h0 = __floats2half2_rn(v.x, v.y);
        __half2 h1 = __floats2half2_rn(v.z, v.w);
        uint2 st;
        st.x = *(unsigned*)&h0;
        st.y = *(unsigned*)&h1;
        *(uint2*)(g_xh + 4 * i) = st;
    }
}

__global__ void wconv_kernel(const float* __restrict__ b1, const float* __restrict__ r1,
                             const float* __restrict__ w1, const float* __restrict__ b2,
                             const float* __restrict__ r2, const float* __restrict__ w2) {
    int i = blockIdx.x * 256 + threadIdx.x;
    if (i < 16384)      g_w1h[i] = __float2half(b1[i]);
    else if (i < 20480) g_w1h[i] = __float2half(r1[i - 16384]);
    else if (i < 28672) g_wg1h[i - 20480] = __float2half(w1[i - 20480]);
    else if (i < 45056) g_w2h[i - 28672] = __float2half(b2[i - 28672]);
    else if (i < 49152) g_w2h[i - 28672] = __float2half(r2[i - 45056]);
    else if (i < 51200) g_wg2h[i - 49152] = __float2half(w2[i - 49152]);
}

// ---------------- RGCN: warp-per-node gather (fp16 rows) -> z[n, BB*IN] (fp16) ----------------
template <int IN, int WPB>
__global__ __launch_bounds__(32 * WPB) void rgcn_gather_z(
    const __half* __restrict__ x, const float* __restrict__ comp) {
    const int VW = IN / 32;
    __shared__ float wsh[WPB][RR * BB];
    int wid = threadIdx.x >> 5, lane = threadIdx.x & 31;
    int n = blockIdx.x * WPB + wid;
    if (n >= NN) return;

    if (lane < RR) {
        float ic = 1.f / fmaxf((float)g_cnt[n * RR + lane], 1.f);
#pragma unroll
        for (int b = 0; b < BB; b++) wsh[wid][lane * BB + b] = comp[lane * BB + b] * ic;
    }
    __syncwarp();

    float acc[BB][VW];
#pragma unroll
    for (int b = 0; b < BB; b++)
#pragma unroll
        for (int c = 0; c < VW; c++) acc[b][c] = 0.f;

    int k1 = g_row_off[n + 1];
    int k = g_row_off[n];
    for (; k + 4 <= k1; k += 4) {
        int v[4];
        float xr[4][VW];
#pragma unroll
        for (int j = 0; j < 4; j++) {
            v[j] = g_adj[k + j];
            ldvh<VW>(xr[j], x + (size_t)(v[j] & 0xFFFF) * IN + VW * lane);
        }
#pragma unroll
        for (int j = 0; j < 4; j++) {
            const float* w = &wsh[wid][(v[j] >> 16) * BB];
#pragma unroll
            for (int b = 0; b < BB; b++)
#pragma unroll
                for (int c = 0; c < VW; c++) acc[b][c] += w[b] * xr[j][c];
        }
    }
    for (; k < k1; k++) {
        int v = g_adj[k];
        float xr[VW];
        ldvh<VW>(xr, x + (size_t)(v & 0xFFFF) * IN + VW * lane);
        const float* w = &wsh[wid][(v >> 16) * BB];
#pragma unroll
        for (int b = 0; b < BB; b++)
#pragma unroll
            for (int c = 0; c < VW; c++) acc[b][c] += w[b] * xr[c];
    }
    __half* zp = g_z + (size_t)n * (BB * IN);
#pragma unroll
    for (int b = 0; b < BB; b++) {
        if (VW == 2) {
            __half2 o = __floats2half2_rn(acc[b][0], acc[b][1]);
            *(__half2*)(zp + b * IN + 2 * lane) = o;
        } else {
            __half2 o0 = __floats2half2_rn(acc[b][0], acc[b][1]);
            __half2 o1 = __floats2half2_rn(acc[b][VW - 2], acc[b][VW - 1]);
            uint2 st;
            st.x = *(unsigned*)&o0;
            st.y = *(unsigned*)&o1;
            *(uint2*)(zp + b * IN + 4 * lane) = st;
        }
    }
}

// ---------------- tensor-core GEMM (all-fp16 I/O) ----------------
// Hout = [A1 | A2](fp16) @ W(fp16). MODE 0: fp16 out + bias + relu.
// MODE 1: fp16 out + fused attention logits -> g_al. 128 threads, 4 warps.
template <int K1, int K2, int N, int WSPLIT, int MODE, int CH>
__global__ __launch_bounds__(128) void tgemm(
    const __half* __restrict__ A1, const __half* __restrict__ A2,
    const __half* __restrict__ W, const float* __restrict__ bias,
    __half* __restrict__ Hout,
    const float* __restrict__ asrc, const float* __restrict__ adst) {
    const int MT = 64 / WSPLIT;
    const int LDA = 40;
    const int LDB = N + 8;
    const int NW = N / (8 * WSPLIT);
    __shared__ __half At[MT * LDA];
    __shared__ __half Wt[32 * LDB];
    int tid = threadIdx.x;
    int wid = tid >> 5, lane = tid & 31;
    int warp_m = wid / WSPLIT, warp_n = wid % WSPLIT;
    int colbase = warp_n * (N / WSPLIT);
    int m0 = blockIdx.x * MT;

    float acc[NW][4];
#pragma unroll
    for (int i = 0; i < NW; i++)
#pragma unroll
        for (int j = 0; j < 4; j++) acc[i][j] = 0.f;

    unsigned sA = (unsigned)__cvta_generic_to_shared(At);
    unsigned sB = (unsigned)__cvta_generic_to_shared(Wt);

    const int T1 = K1 / 32, T2 = K2 / 32;
    for (int t = 0; t < T1 + T2; t++) {
        const __half* A;
        int ks, kstride;
        if (t < T1) { A = A1; ks = t * 32; kstride = K1; }
        else        { A = A2; ks = (t - T1) * 32; kstride = K2; }
        int wks = t * 32;
        __syncthreads();
        for (int idx = tid; idx < MT * 8; idx += 128) {
            int m = idx >> 3, q = idx & 7;
            int gm = m0 + m; if (gm >= NN) gm = NN - 1;
            uint2 v = __ldg((const uint2*)(A + (size_t)gm * kstride + ks + 4 * q));
            *(uint2*)&At[m * LDA + 4 * q] = v;
        }
        for (int idx = tid; idx < 32 * N / 4; idx += 128) {
            int row = idx / (N / 4), cq = idx % (N / 4);
            uint2 v = __ldg((const uint2*)(W + (size_t)(wks + row) * N + 4 * cq));
            *(uint2*)&Wt[row * LDB + 4 * cq] = v;
        }
        __syncthreads();
#pragma unroll
        for (int k16 = 0; k16 < 2; k16++) {
            unsigned a0, a1, a2, a3;
            unsigned aaddr = sA + ((warp_m * 16 + (lane & 15)) * LDA + k16 * 16 + (lane >> 4) * 8) * 2;
            ldsm4(a0, a1, a2, a3, aaddr);
#pragma unroll
            for (int tp = 0; tp < NW / 2; tp++) {
                int n0 = colbase + tp * 16;
                unsigned b0, b1, b2, b3;
                unsigned baddr = sB + ((k16 * 16 + (lane & 15)) * LDB + n0 + (lane >> 4) * 8) * 2;
                ldsm4t(b0, b1, b2, b3, baddr);
                mma16816(acc[2 * tp], a0, a1, a2, a3, b0, b1);
                mma16816(acc[2 * tp + 1], a0, a1, a2, a3, b2, b3);
            }
        }
    }
    // epilogue
    int r0 = m0 + warp_m * 16 + (lane >> 2);
    int r1 = r0 + 8;
    if (MODE == 0) {
#pragma unroll
        for (int tn = 0; tn < NW; tn++) {
            int c = colbase + 8 * tn + 2 * (lane & 3);
            float2 bv = ld2(bias + c);
            if (r0 < NN) {
                __half2 o = __floats2half2_rn(fmaxf(acc[tn][0] + bv.x, 0.f),
                                              fmaxf(acc[tn][1] + bv.y, 0.f));
                *(__half2*)(Hout + (size_t)r0 * N + c) = o;
            }
            if (r1 < NN) {
                __half2 o = __floats2half2_rn(fmaxf(acc[tn][2] + bv.x, 0.f),
                                              fmaxf(acc[tn][3] + bv.y, 0.f));
                *(__half2*)(Hout + (size_t)r1 * N + c) = o;
            }
        }
    } else {
        const int NH = N / (WSPLIT * CH);  // heads per warp
        float ps0[NH], pd0[NH], ps1[NH], pd1[NH];
#pragma unroll
        for (int i = 0; i < NH; i++) { ps0[i] = pd0[i] = ps1[i] = pd1[i] = 0.f; }
#pragma unroll
        for (int tn = 0; tn < NW; tn++) {
            int c = colbase + 8 * tn + 2 * (lane & 3);
            if (r0 < NN) {
                __half2 o = __floats2half2_rn(acc[tn][0], acc[tn][1]);
                *(__half2*)(Hout + (size_t)r0 * N + c) = o;
            }
            if (r1 < NN) {
                __half2 o = __floats2half2_rn(acc[tn][2], acc[tn][3]);
                *(__half2*)(Hout + (size_t)r1 * N + c) = o;
            }
            float2 a = ld2(asrc + c);
            float2 d = ld2(adst + c);
            int hl = (8 * tn) / CH;
            ps0[hl] += acc[tn][0] * a.x + acc[tn][1] * a.y;
            pd0[hl] += acc[tn][0] * d.x + acc[tn][1] * d.y;
            ps1[hl] += acc[tn][2] * a.x + acc[tn][3] * a.y;
            pd1[hl] += acc[tn][2] * d.x + acc[tn][3] * d.y;
        }
#pragma unroll
        for (int hl = 0; hl < NH; hl++) {
            float a0 = ps0[hl], b0 = pd0[hl], a1 = ps1[hl], b1 = pd1[hl];
            a0 += __shfl_xor_sync(0xffffffffu, a0, 1);
            b0 += __shfl_xor_sync(0xffffffffu, b0, 1);
            a1 += __shfl_xor_sync(0xffffffffu, a1, 1);
            b1 += __shfl_xor_sync(0xffffffffu, b1, 1);
            a0 += __shfl_xor_sync(0xffffffffu, a0, 2);
            b0 += __shfl_xor_sync(0xffffffffu, b0, 2);
            a1 += __shfl_xor_sync(0xffffffffu, a1, 2);
            b1 += __shfl_xor_sync(0xffffffffu, b1, 2);
            if ((lane & 3) == 0) {
                int hg = colbase / CH + hl;
                if (r0 < NN) {
                    g_al[(size_t)r0 * 8 + hg] = a0;
                    g_al[(size_t)r0 * 8 + 4 + hg] = b0;
                }
                if (r1 < NN) {
                    g_al[(size_t)r1 * 8 + hg] = a1;
                    g_al[(size_t)r1 * 8 + 4 + hg] = b1;
                }
            }
        }
    }
}

// ---------------- per-edge softmax numerators ----------------
__device__ __forceinline__ float lrexp(float v) {
    v = v > 0.f ? v : 0.2f * v;
    return __expf(v);
}

__global__ void ev_kernel(const int* __restrict__ src, const int* __restrict__ dst) {
    int e = blockIdx.x * blockDim.x + threadIdx.x;
    if (e >= EE) return;
    int s = src[e], d = dst[e], pos = g_pos[e];
    float4 as = *(const float4*)(g_al + (size_t)s * 8);
    float4 ad = *(const float4*)(g_al + (size_t)d * 8 + 4);
    float4 ev;
    ev.x = lrexp(as.x + ad.x);
    ev.y = lrexp(as.y + ad.y);
    ev.z = lrexp(as.z + ad.z);
    ev.w = lrexp(as.w + ad.w);
    *(float4*)(g_ev + (size_t)pos * 4) = ev;
}

// ---------------- GAT gather: warp-per-node, sync-free, fp16 rows ----------------
template <int WPB>
__global__ __launch_bounds__(32 * WPB) void gat_concat_warp(
    const float* __restrict__ bias, __half* __restrict__ outh) {
    int wid = threadIdx.x >> 5, lane = threadIdx.x & 31;
    int n = blockIdx.x * WPB + wid;
    if (n >= NN) return;
    int h = lane >> 3;
    float4 acc = make_float4(0.f, 0.f, 0.f, 0.f);
    float z = 0.f;
    int k1 = g_row_off[n + 1];
    int k = g_row_off[n];
    for (; k + 4 <= k1; k += 4) {
        int s0 = g_adj[k + 0] & 0xFFFF, s1 = g_adj[k + 1] & 0xFFFF;
        int s2 = g_adj[k + 2] & 0xFFFF, s3 = g_adj[k + 3] & 0xFFFF;
        float e0 = __ldg(g_ev + (size_t)(k + 0) * 4 + h);
        float e1 = __ldg(g_ev + (size_t)(k + 1) * 4 + h);
        float e2 = __ldg(g_ev + (size_t)(k + 2) * 4 + h);
        float e3 = __ldg(g_ev + (size_t)(k + 3) * 4 + h);
        float4 h0 = ldh4(g_h + (size_t)s0 * 128 + 4 * lane);
        float4 h1 = ldh4(g_h + (size_t)s1 * 128 + 4 * lane);
        float4 h2 = ldh4(g_h + (size_t)s2 * 128 + 4 * lane);
        float4 h3 = ldh4(g_h + (size_t)s3 * 128 + 4 * lane);
        z += (e0 + e1) + (e2 + e3);
        acc.x += e0 * h0.x + e1 * h1.x + e2 * h2.x + e3 * h3.x;
        acc.y += e0 * h0.y + e1 * h1.y + e2 * h2.y + e3 * h3.y;
        acc.z += e0 * h0.z + e1 * h1.z + e2 * h2.z + e3 * h3.z;
        acc.w += e0 * h0.w + e1 * h1.w + e2 * h2.w + e3 * h3.w;
    }
    for (; k < k1; k++) {
        int s = g_adj[k] & 0xFFFF;
        float e = __ldg(g_ev + (size_t)k * 4 + h);
        float4 hv = ldh4(g_h + (size_t)s * 128 + 4 * lane);
        z += e;
        acc.x += e * hv.x; acc.y += e * hv.y; acc.z += e * hv.z; acc.w += e * hv.w;
    }
    {   // self loop
        float e = lrexp(g_al[(size_t)n * 8 + h] + g_al[(size_t)n * 8 + 4 + h]);
        float4 hv = ldh4(g_h + (size_t)n * 128 + 4 * lane);
        z += e;
        acc.x += e * hv.x; acc.y += e * hv.y; acc.z += e * hv.z; acc.w += e * hv.w;
    }
    float inv = 1.f / z;
    float4 b = __ldg((const float4*)bias + lane);
    __half2 c0 = __floats2half2_rn(acc.x * inv + b.x, acc.y * inv + b.y);
    __half2 c1 = __floats2half2_rn(acc.z * inv + b.z, acc.w * inv + b.w);
    uint2 st;
    st.x = *(unsigned*)&c0;
    st.y = *(unsigned*)&c1;
    *(uint2*)(outh + (size_t)n * 128 + 4 * lane) = st;
}

template <int WPB>
__global__ __launch_bounds__(32 * WPB) void gat_mean_warp(
    const float* __restrict__ bias, float* __restrict__ out) {
    int wid = threadIdx.x >> 5, lane = threadIdx.x & 31;
    int n = blockIdx.x * WPB + wid;
    if (n >= NN) return;
    int h = lane >> 3;
    float ax = 0.f, ay = 0.f, z = 0.f;
    int k1 = g_row_off[n + 1];
    int k = g_row_off[n];
    for (; k + 4 <= k1; k += 4) {
        int s0 = g_adj[k + 0] & 0xFFFF, s1 = g_adj[k + 1] & 0xFFFF;
        int s2 = g_adj[k + 2] & 0xFFFF, s3 = g_adj[k + 3] & 0xFFFF;
        float e0 = __ldg(g_ev + (size_t)(k + 0) * 4 + h);
        float e1 = __ldg(g_ev + (size_t)(k + 1) * 4 + h);
        float e2 = __ldg(g_ev + (size_t)(k + 2) * 4 + h);
        float e3 = __ldg(g_ev + (size_t)(k + 3) * 4 + h);
        float2 h0 = ldh2(g_h + (size_t)s0 * 64 + 2 * lane);
        float2 h1 = ldh2(g_h + (size_t)s1 * 64 + 2 * lane);
        float2 h2 = ldh2(g_h + (size_t)s2 * 64 + 2 * lane);
        float2 h3 = ldh2(g_h + (size_t)s3 * 64 + 2 * lane);
        z += (e0 + e1) + (e2 + e3);
        ax += e0 * h0.x + e1 * h1.x + e2 * h2.x + e3 * h3.x;
        ay += e0 * h0.y + e1 * h1.y + e2 * h2.y + e3 * h3.y;
    }
    for (; k < k1; k++) {
        int s = g_adj[k] & 0xFFFF;
        float e = __ldg(g_ev + (size_t)k * 4 + h);
        float2 hv = ldh2(g_h + (size_t)s * 64 + 2 * lane);
        z += e;
        ax += e * hv.x;
        ay += e * hv.y;
    }
    {   // self loop
        float e = lrexp(g_al[(size_t)n * 8 + h] + g_al[(size_t)n * 8 + 4 + h]);
        float2 hv = ldh2(g_h + (size_t)n * 64 + 2 * lane);
        z += e;
        ax += e * hv.x;
        ay += e * hv.y;
    }
    float inv = 1.f / z;
    float vx = ax * inv, vy = ay * inv;
    vx += __shfl_xor_sync(0xffffffffu, vx, 8);
    vy += __shfl_xor_sync(0xffffffffu, vy, 8);
    vx += __shfl_xor_sync(0xffffffffu, vx, 16);
    vy += __shfl_xor_sync(0xffffffffu, vy, 16);
    if (lane < 8) {
        int c = 2 * lane;
        float sx = vx * 0.25f + __ldg(bias + c);
        float sy = vy * 0.25f + __ldg(bias + c + 1);
        sx = fmaxf(sx, 0.f);
        sy = fmaxf(sy, 0.f);
        float2 o;
        o.x = tanhf(sx);
        o.y = tanhf(sy);
        *(float2*)(out + (size_t)n * 16 + c) = o;
    }
}

// ---------------- launch ----------------
extern "C" void kernel_launch(void* const* d_in, const int* in_sizes, int n_in,
                              void* d_out, int out_size) {
    const float* x      = (const float*)d_in[0];
    const int*   ei     = (const int*)d_in[1];
    const int*   et     = (const int*)d_in[2];
    const float* basis1 = (const float*)d_in[3];
    const float* comp1  = (const float*)d_in[4];
    const float* root1  = (const float*)d_in[5];
    const float* brg1   = (const float*)d_in[6];
    const float* wg1    = (const float*)d_in[7];
    const float* asrc1  = (const float*)d_in[8];
    const float* adst1  = (const float*)d_in[9];
    const float* bg1    = (const float*)d_in[10];
    const float* basis2 = (const float*)d_in[11];
    const float* comp2  = (const float*)d_in[12];
    const float* root2  = (const float*)d_in[13];
    const float* brg2   = (const float*)d_in[14];
    const float* wg2    = (const float*)d_in[15];
    const float* asrc2  = (const float*)d_in[16];
    const float* adst2  = (const float*)d_in[17];
    const float* bg2    = (const float*)d_in[18];
    float* out = (float*)d_out;
    const int* src = ei;
    const int* dst = ei + EE;

    int* p_cnt;
    __half *p_xh, *p_x1h, *p_x2h, *p_x3h, *p_h, *p_w1h, *p_wg1h, *p_w2h, *p_wg2h, *p_z;
    cudaGetSymbolAddress((void**)&p_cnt, g_cnt);
    cudaGetSymbolAddress((void**)&p_z, g_z);
    cudaGetSymbolAddress((void**)&p_xh, g_xh);
    cudaGetSymbolAddress((void**)&p_x1h, g_x1h);
    cudaGetSymbolAddress((void**)&p_x2h, g_x2h);
    cudaGetSymbolAddress((void**)&p_x3h, g_x3h);
    cudaGetSymbolAddress((void**)&p_h, g_h);
    cudaGetSymbolAddress((void**)&p_w1h, g_w1h);
    cudaGetSymbolAddress((void**)&p_wg1h, g_wg1h);
    cudaGetSymbolAddress((void**)&p_w2h, g_w2h);
    cudaGetSymbolAddress((void**)&p_wg2h, g_wg2h);

    // --- CSR build + one-time fp16 conversions ---
    zero_int<<<(NN * RR + 255) / 256, 256>>>(p_cnt, NN * RR);
    hist_kernel<<<(EE + 255) / 256, 256>>>(dst, et);
    scanA<<<NB, 256>>>();
    scanB<<<1, 256>>>();
    scanC<<<NB, 256>>>();
    fill_kernel<<<(EE + 255) / 256, 256>>>(src, dst, et);
    x_half_kernel<<<(NN * 16 + 255) / 256, 256>>>(x);
    wconv_kernel<<<(51200 + 255) / 256, 256>>>(basis1, root1, wg1, basis2, root2, wg2);

    const int WPB = 4;
    int nblk = (NN + WPB - 1) / WPB;

    // ---- RGCN 1: 64 -> 64, relu (fp16 out) ----
    rgcn_gather_z<64, WPB><<<nblk, 32 * WPB>>>(p_xh, comp1);
    tgemm<256, 64, 64, 1, 0, 32><<<(NN + 63) / 64, 128>>>(
        p_z, p_xh, p_w1h, brg1, p_x1h, nullptr, nullptr);
    // ---- GAT 1: 64 -> 4x32 concat ----
    tgemm<64, 0, 128, 2, 1, 32><<<(NN + 31) / 32, 128>>>(
        p_x1h, nullptr, p_wg1h, nullptr, p_h, asrc1, adst1);
    ev_kernel<<<(EE + 255) / 256, 256>>>(src, dst);
    gat_concat_warp<WPB><<<nblk, 32 * WPB>>>(bg1, p_x2h);
    // ---- RGCN 2: 128 -> 32, relu (fp16 out) ----
    rgcn_gather_z<128, WPB><<<nblk, 32 * WPB>>>(p_x2h, comp2);
    tgemm<512, 128, 32, 1, 0, 32><<<(NN + 63) / 64, 128>>>(
        p_z, p_x2h, p_w2h, brg2, p_x3h, nullptr, nullptr);
    // ---- GAT 2: 32 -> 4x16, mean heads, relu, tanh ----
    tgemm<32, 0, 64, 1, 1, 16><<<(NN + 63) / 64, 128>>>(
        p_x3h, nullptr, p_wg2h, nullptr, p_h, asrc2, adst2);
    ev_kernel<<<(EE + 255) / 256, 256>>>(src, dst);
    gat_mean_warp<WPB><<<nblk, 32 * WPB>>>(bg2, out);
}

// round 16
// speedup vs baseline: 1.0474x; 1.0474x over previous
#include <cuda_runtime.h>
#include <cuda_fp16.h>
#include <math.h>

#define NN 50000
#define EE 800000
#define RR 8
#define BB 4
#define NB ((NN + 255) / 256)

// ---------------- scratch (device globals; no allocation) ----------------
__device__ __half g_xh[NN * 64];        // fp16 input x
__device__ __half g_x1h[NN * 64];       // after RGCN1 (fp16)
__device__ __half g_x2h[NN * 128];      // after GAT1 (fp16)
__device__ __half g_x3h[NN * 32];       // after RGCN2 (fp16)
__device__ __half g_h[NN * 128];        // GAT transformed features (fp16)
__device__ float  g_al[NN * 8];
__device__ __half g_z[(size_t)NN * 512];  // B-space aggregates (fp16)
__device__ int    g_cnt[NN * RR];
__device__ int    g_row_start[NN];
__device__ int    g_row_end[NN];
__device__ int    g_cursor[NN];
__device__ int    g_grand;
__device__ int    g_adj[EE];            // src | (etype<<16)
__device__ int    g_pos[EE];
__device__ float  g_ev[(size_t)EE * 4];
__device__ __half g_w1h[320 * 64];
__device__ __half g_wg1h[64 * 128];
__device__ __half g_w2h[640 * 32];
__device__ __half g_wg2h[32 * 64];

__device__ __forceinline__ float4 ld4(const float* p) { return __ldg((const float4*)p); }
__device__ __forceinline__ float2 ld2(const float* p) { return __ldg((const float2*)p); }

__device__ __forceinline__ float4 ldh4(const __half* p) {
    uint2 raw = __ldg((const uint2*)p);
    __half2 a = *(__half2*)&raw.x;
    __half2 b = *(__half2*)&raw.y;
    float2 fa = __half22float2(a), fb = __half22float2(b);
    return make_float4(fa.x, fa.y, fb.x, fb.y);
}
__device__ __forceinline__ float2 ldh2(const __half* p) {
    __half2 h = __ldg((const __half2*)p);
    return __half22float2(h);
}

template <int VW>
__device__ __forceinline__ void ldvh(float (&d)[VW], const __half* p) {
    if (VW == 2) {
        float2 v = ldh2(p);
        d[0] = v.x; d[1] = v.y;
    } else {
        float4 v = ldh4(p);
        d[0] = v.x; d[1] = v.y; d[2] = v.z; d[3] = v.w;
    }
}

// ---------------- tensor-core primitives ----------------
__device__ __forceinline__ void ldsm4(unsigned& r0, unsigned& r1, unsigned& r2, unsigned& r3,
                                      unsigned addr) {
    asm volatile("ldmatrix.sync.aligned.m8n8.x4.shared.b16 {%0,%1,%2,%3}, [%4];"
                 : "=r"(r0), "=r"(r1), "=r"(r2), "=r"(r3) : "r"(addr));
}
__device__ __forceinline__ void ldsm4t(unsigned& r0, unsigned& r1, unsigned& r2, unsigned& r3,
                                       unsigned addr) {
    asm volatile("ldmatrix.sync.aligned.m8n8.x4.trans.shared.b16 {%0,%1,%2,%3}, [%4];"
                 : "=r"(r0), "=r"(r1), "=r"(r2), "=r"(r3) : "r"(addr));
}
__device__ __forceinline__ void mma16816(float* d, unsigned a0, unsigned a1, unsigned a2, unsigned a3,
                                         unsigned b0, unsigned b1) {
    asm volatile("mma.sync.aligned.m16n8k16.row.col.f32.f16.f16.f32 "
                 "{%0,%1,%2,%3},{%4,%5,%6,%7},{%8,%9},{%0,%1,%2,%3};"
                 : "+f"(d[0]), "+f"(d[1]), "+f"(d[2]), "+f"(d[3])
                 : "r"(a0), "r"(a1), "r"(a2), "r"(a3), "r"(b0), "r"(b1));
}

// ---------------- CSR build ----------------
__global__ void zero_cnt() {
    int i = blockIdx.x * blockDim.x + threadIdx.x;
    if (i < NN * RR) g_cnt[i] = 0;
    if (i == 0) g_grand = 0;
}

__global__ void hist_kernel(const int* __restrict__ dst, const int* __restrict__ et) {
    int e = blockIdx.x * blockDim.x + threadIdx.x;
    if (e < EE) atomicAdd(&g_cnt[dst[e] * RR + et[e]], 1);
}

// fused scan: per-block exclusive scan + atomic base allocation (block order arbitrary)
__global__ void scan_fused() {
    __shared__ int sh[256];
    __shared__ int base_sh;
    int t = threadIdx.x;
    int n = blockIdx.x * 256 + t;
    int deg = 0;
    if (n < NN) {
#pragma unroll
        for (int r = 0; r < RR; r++) deg += g_cnt[n * RR + r];
    }
    int val = deg;
    sh[t] = val;
    __syncthreads();
    for (int d = 1; d < 256; d <<= 1) {
        int a = (t >= d) ? sh[t - d] : 0;
        __syncthreads();
        val += a;
        sh[t] = val;
        __syncthreads();
    }
    if (t == 255) base_sh = atomicAdd(&g_grand, val);
    __syncthreads();
    if (n < NN) {
        int start = base_sh + val - deg;
        g_row_start[n] = start;
        g_row_end[n] = start + deg;
        g_cursor[n] = start;
    }
}

__global__ void fill_kernel(const int* __restrict__ src, const int* __restrict__ dst,
                            const int* __restrict__ et) {
    int e = blockIdx.x * blockDim.x + threadIdx.x;
    if (e < EE) {
        int d = dst[e];
        int pos = atomicAdd(&g_cursor[d], 1);
        g_adj[pos] = src[e] | (et[e] << 16);
        g_pos[e] = pos;
    }
}

// ---------------- fp16 conversions (once per launch, fused) ----------------
__global__ void conv_kernel(const float* __restrict__ x,
                            const float* __restrict__ b1, const float* __restrict__ r1,
                            const float* __restrict__ w1, const float* __restrict__ b2,
                            const float* __restrict__ r2, const float* __restrict__ w2) {
    int i = blockIdx.x * blockDim.x + threadIdx.x;
    if (i < NN * 64 / 4) {
        float4 v = ld4(x + 4 * i);
        __half2 h0 = __floats2half2_rn(v.x, v.y);
        __half2 h1 = __floats2half2_rn(v.z, v.w);
        uint2 st;
        st.x = *(unsigned*)&h0;
        st.y = *(unsigned*)&h1;
        *(uint2*)(g_xh + 4 * i) = st;
    }
    if (i < 16384)      g_w1h[i] = __float2half(b1[i]);
    else if (i < 20480) g_w1h[i] = __float2half(r1[i - 16384]);
    else if (i < 28672) g_wg1h[i - 20480] = __float2half(w1[i - 20480]);
    else if (i < 45056) g_w2h[i - 28672] = __float2half(b2[i - 28672]);
    else if (i < 49152) g_w2h[i - 28672] = __float2half(r2[i - 45056]);
    else if (i < 51200) g_wg2h[i - 49152] = __float2half(w2[i - 49152]);
}

// ---------------- RGCN: warp-per-node gather (fp16 rows) -> z[n, BB*IN] (fp16) ----------------
template <int IN, int WPB, int UN>
__global__ __launch_bounds__(32 * WPB) void rgcn_gather_z(
    const __half* __restrict__ x, const float* __restrict__ comp) {
    const int VW = IN / 32;
    __shared__ float wsh[WPB][RR * BB];
    int wid = threadIdx.x >> 5, lane = threadIdx.x & 31;
    int n = blockIdx.x * WPB + wid;
    if (n >= NN) return;

    if (lane < RR) {
        float ic = 1.f / fmaxf((float)g_cnt[n * RR + lane], 1.f);
#pragma unroll
        for (int b = 0; b < BB; b++) wsh[wid][lane * BB + b] = comp[lane * BB + b] * ic;
    }
    __syncwarp();

    float acc[BB][VW];
#pragma unroll
    for (int b = 0; b < BB; b++)
#pragma unroll
        for (int c = 0; c < VW; c++) acc[b][c] = 0.f;

    int k1 = g_row_end[n];
    int k = g_row_start[n];
    if (UN == 8) {
        for (; k + 8 <= k1; k += 8) {
            int v[8];
            float xr[8][VW];
#pragma unroll
            for (int j = 0; j < 8; j++) {
                v[j] = g_adj[k + j];
                ldvh<VW>(xr[j], x + (size_t)(v[j] & 0xFFFF) * IN + VW * lane);
            }
#pragma unroll
            for (int j = 0; j < 8; j++) {
                const float* w = &wsh[wid][(v[j] >> 16) * BB];
#pragma unroll
                for (int b = 0; b < BB; b++)
#pragma unroll
                    for (int c = 0; c < VW; c++) acc[b][c] += w[b] * xr[j][c];
            }
        }
    }
    for (; k + 4 <= k1; k += 4) {
        int v[4];
        float xr[4][VW];
#pragma unroll
        for (int j = 0; j < 4; j++) {
            v[j] = g_adj[k + j];
            ldvh<VW>(xr[j], x + (size_t)(v[j] & 0xFFFF) * IN + VW * lane);
        }
#pragma unroll
        for (int j = 0; j < 4; j++) {
            const float* w = &wsh[wid][(v[j] >> 16) * BB];
#pragma unroll
            for (int b = 0; b < BB; b++)
#pragma unroll
                for (int c = 0; c < VW; c++) acc[b][c] += w[b] * xr[j][c];
        }
    }
    for (; k < k1; k++) {
        int v = g_adj[k];
        float xr[VW];
        ldvh<VW>(xr, x + (size_t)(v & 0xFFFF) * IN + VW * lane);
        const float* w = &wsh[wid][(v >> 16) * BB];
#pragma unroll
        for (int b = 0; b < BB; b++)
#pragma unroll
            for (int c = 0; c < VW; c++) acc[b][c] += w[b] * xr[c];
    }
    __half* zp = g_z + (size_t)n * (BB * IN);
#pragma unroll
    for (int b = 0; b < BB; b++) {
        if (VW == 2) {
            __half2 o = __floats2half2_rn(acc[b][0], acc[b][1]);
            *(__half2*)(zp + b * IN + 2 * lane) = o;
        } else {
            __half2 o0 = __floats2half2_rn(acc[b][0], acc[b][1]);
            __half2 o1 = __floats2half2_rn(acc[b][VW - 2], acc[b][VW - 1]);
            uint2 st;
            st.x = *(unsigned*)&o0;
            st.y = *(unsigned*)&o1;
            *(uint2*)(zp + b * IN + 4 * lane) = st;
        }
    }
}

// ---------------- tensor-core GEMM (all-fp16 I/O) ----------------
template <int K1, int K2, int N, int WSPLIT, int MODE, int CH>
__global__ __launch_bounds__(128) void tgemm(
    const __half* __restrict__ A1, const __half* __restrict__ A2,
    const __half* __restrict__ W, const float* __restrict__ bias,
    __half* __restrict__ Hout,
    const float* __restrict__ asrc, const float* __restrict__ adst) {
    const int MT = 64 / WSPLIT;
    const int LDA = 40;
    const int LDB = N + 8;
    const int NW = N / (8 * WSPLIT);
    __shared__ __half At[MT * LDA];
    __shared__ __half Wt[32 * LDB];
    int tid = threadIdx.x;
    int wid = tid >> 5, lane = tid & 31;
    int warp_m = wid / WSPLIT, warp_n = wid % WSPLIT;
    int colbase = warp_n * (N / WSPLIT);
    int m0 = blockIdx.x * MT;

    float acc[NW][4];
#pragma unroll
    for (int i = 0; i < NW; i++)
#pragma unroll
        for (int j = 0; j < 4; j++) acc[i][j] = 0.f;

    unsigned sA = (unsigned)__cvta_generic_to_shared(At);
    unsigned sB = (unsigned)__cvta_generic_to_shared(Wt);

    const int T1 = K1 / 32, T2 = K2 / 32;
    for (int t = 0; t < T1 + T2; t++) {
        const __half* A;
        int ks, kstride;
        if (t < T1) { A = A1; ks = t * 32; kstride = K1; }
        else        { A = A2; ks = (t - T1) * 32; kstride = K2; }
        int wks = t * 32;
        __syncthreads();
        for (int idx = tid; idx < MT * 8; idx += 128) {
            int m = idx >> 3, q = idx & 7;
            int gm = m0 + m; if (gm >= NN) gm = NN - 1;
            uint2 v = __ldg((const uint2*)(A + (size_t)gm * kstride + ks + 4 * q));
            *(uint2*)&At[m * LDA + 4 * q] = v;
        }
        for (int idx = tid; idx < 32 * N / 4; idx += 128) {
            int row = idx / (N / 4), cq = idx % (N / 4);
            uint2 v = __ldg((const uint2*)(W + (size_t)(wks + row) * N + 4 * cq));
            *(uint2*)&Wt[row * LDB + 4 * cq] = v;
        }
        __syncthreads();
#pragma unroll
        for (int k16 = 0; k16 < 2; k16++) {
            unsigned a0, a1, a2, a3;
            unsigned aaddr = sA + ((warp_m * 16 + (lane & 15)) * LDA + k16 * 16 + (lane >> 4) * 8) * 2;
            ldsm4(a0, a1, a2, a3, aaddr);
#pragma unroll
            for (int tp = 0; tp < NW / 2; tp++) {
                int n0 = colbase + tp * 16;
                unsigned b0, b1, b2, b3;
                unsigned baddr = sB + ((k16 * 16 + (lane & 15)) * LDB + n0 + (lane >> 4) * 8) * 2;
                ldsm4t(b0, b1, b2, b3, baddr);
                mma16816(acc[2 * tp], a0, a1, a2, a3, b0, b1);
                mma16816(acc[2 * tp + 1], a0, a1, a2, a3, b2, b3);
            }
        }
    }
    // epilogue
    int r0 = m0 + warp_m * 16 + (lane >> 2);
    int r1 = r0 + 8;
    if (MODE == 0) {
#pragma unroll
        for (int tn = 0; tn < NW; tn++) {
            int c = colbase + 8 * tn + 2 * (lane & 3);
            float2 bv = ld2(bias + c);
            if (r0 < NN) {
                __half2 o = __floats2half2_rn(fmaxf(acc[tn][0] + bv.x, 0.f),
                                              fmaxf(acc[tn][1] + bv.y, 0.f));
                *(__half2*)(Hout + (size_t)r0 * N + c) = o;
            }
            if (r1 < NN) {
                __half2 o = __floats2half2_rn(fmaxf(acc[tn][2] + bv.x, 0.f),
                                              fmaxf(acc[tn][3] + bv.y, 0.f));
                *(__half2*)(Hout + (size_t)r1 * N + c) = o;
            }
        }
    } else {
        const int NH = N / (WSPLIT * CH);  // heads per warp
        float ps0[NH], pd0[NH], ps1[NH], pd1[NH];
#pragma unroll
        for (int i = 0; i < NH; i++) { ps0[i] = pd0[i] = ps1[i] = pd1[i] = 0.f; }
#pragma unroll
        for (int tn = 0; tn < NW; tn++) {
            int c = colbase + 8 * tn + 2 * (lane & 3);
            if (r0 < NN) {
                __half2 o = __floats2half2_rn(acc[tn][0], acc[tn][1]);
                *(__half2*)(Hout + (size_t)r0 * N + c) = o;
            }
            if (r1 < NN) {
                __half2 o = __floats2half2_rn(acc[tn][2], acc[tn][3]);
                *(__half2*)(Hout + (size_t)r1 * N + c) = o;
            }
            float2 a = ld2(asrc + c);
            float2 d = ld2(adst + c);
            int hl = (8 * tn) / CH;
            ps0[hl] += acc[tn][0] * a.x + acc[tn][1] * a.y;
            pd0[hl] += acc[tn][0] * d.x + acc[tn][1] * d.y;
            ps1[hl] += acc[tn][2] * a.x + acc[tn][3] * a.y;
            pd1[hl] += acc[tn][2] * d.x + acc[tn][3] * d.y;
        }
#pragma unroll
        for (int hl = 0; hl < NH; hl++) {
            float a0 = ps0[hl], b0 = pd0[hl], a1 = ps1[hl], b1 = pd1[hl];
            a0 += __shfl_xor_sync(0xffffffffu, a0, 1);
            b0 += __shfl_xor_sync(0xffffffffu, b0, 1);
            a1 += __shfl_xor_sync(0xffffffffu, a1, 1);
            b1 += __shfl_xor_sync(0xffffffffu, b1, 1);
            a0 += __shfl_xor_sync(0xffffffffu, a0, 2);
            b0 += __shfl_xor_sync(0xffffffffu, b0, 2);
            a1 += __shfl_xor_sync(0xffffffffu, a1, 2);
            b1 += __shfl_xor_sync(0xffffffffu, b1, 2);
            if ((lane & 3) == 0) {
                int hg = colbase / CH + hl;
                if (r0 < NN) {
                    g_al[(size_t)r0 * 8 + hg] = a0;
                    g_al[(size_t)r0 * 8 + 4 + hg] = b0;
                }
                if (r1 < NN) {
                    g_al[(size_t)r1 * 8 + hg] = a1;
                    g_al[(size_t)r1 * 8 + 4 + hg] = b1;
                }
            }
        }
    }
}

// ---------------- per-edge softmax numerators ----------------
__device__ __forceinline__ float lrexp(float v) {
    v = v > 0.f ? v : 0.2f * v;
    return __expf(v);
}

__global__ void ev_kernel(const int* __restrict__ src, const int* __restrict__ dst) {
    int e = blockIdx.x * blockDim.x + threadIdx.x;
    if (e >= EE) return;
    int s = src[e], d = dst[e], pos = g_pos[e];
    float4 as = *(const float4*)(g_al + (size_t)s * 8);
    float4 ad = *(const float4*)(g_al + (size_t)d * 8 + 4);
    float4 ev;
    ev.x = lrexp(as.x + ad.x);
    ev.y = lrexp(as.y + ad.y);
    ev.z = lrexp(as.z + ad.z);
    ev.w = lrexp(as.w + ad.w);
    *(float4*)(g_ev + (size_t)pos * 4) = ev;
}

// ---------------- GAT gather: warp-per-node, sync-free, fp16 rows ----------------
template <int WPB>
__global__ __launch_bounds__(32 * WPB) void gat_concat_warp(
    const float* __restrict__ bias, __half* __restrict__ outh) {
    int wid = threadIdx.x >> 5, lane = threadIdx.x & 31;
    int n = blockIdx.x * WPB + wid;
    if (n >= NN) return;
    int h = lane >> 3;
    float4 acc = make_float4(0.f, 0.f, 0.f, 0.f);
    float z = 0.f;
    int k1 = g_row_end[n];
    int k = g_row_start[n];
    for (; k + 8 <= k1; k += 8) {
        int s[8];
        float e[8];
        float4 hv[8];
#pragma unroll
        for (int j = 0; j < 8; j++) {
            s[j] = g_adj[k + j] & 0xFFFF;
            e[j] = __ldg(g_ev + (size_t)(k + j) * 4 + h);
        }
#pragma unroll
        for (int j = 0; j < 8; j++) hv[j] = ldh4(g_h + (size_t)s[j] * 128 + 4 * lane);
#pragma unroll
        for (int j = 0; j < 8; j++) {
            z += e[j];
            acc.x += e[j] * hv[j].x;
            acc.y += e[j] * hv[j].y;
            acc.z += e[j] * hv[j].z;
            acc.w += e[j] * hv[j].w;
        }
    }
    for (; k + 4 <= k1; k += 4) {
        int s0 = g_adj[k + 0] & 0xFFFF, s1 = g_adj[k + 1] & 0xFFFF;
        int s2 = g_adj[k + 2] & 0xFFFF, s3 = g_adj[k + 3] & 0xFFFF;
        float e0 = __ldg(g_ev + (size_t)(k + 0) * 4 + h);
        float e1 = __ldg(g_ev + (size_t)(k + 1) * 4 + h);
        float e2 = __ldg(g_ev + (size_t)(k + 2) * 4 + h);
        float e3 = __ldg(g_ev + (size_t)(k + 3) * 4 + h);
        float4 h0 = ldh4(g_h + (size_t)s0 * 128 + 4 * lane);
        float4 h1 = ldh4(g_h + (size_t)s1 * 128 + 4 * lane);
        float4 h2 = ldh4(g_h + (size_t)s2 * 128 + 4 * lane);
        float4 h3 = ldh4(g_h + (size_t)s3 * 128 + 4 * lane);
        z += (e0 + e1) + (e2 + e3);
        acc.x += e0 * h0.x + e1 * h1.x + e2 * h2.x + e3 * h3.x;
        acc.y += e0 * h0.y + e1 * h1.y + e2 * h2.y + e3 * h3.y;
        acc.z += e0 * h0.z + e1 * h1.z + e2 * h2.z + e3 * h3.z;
        acc.w += e0 * h0.w + e1 * h1.w + e2 * h2.w + e3 * h3.w;
    }
    for (; k < k1; k++) {
        int s = g_adj[k] & 0xFFFF;
        float e = __ldg(g_ev + (size_t)k * 4 + h);
        float4 hv = ldh4(g_h + (size_t)s * 128 + 4 * lane);
        z += e;
        acc.x += e * hv.x; acc.y += e * hv.y; acc.z += e * hv.z; acc.w += e * hv.w;
    }
    {   // self loop
        float e = lrexp(g_al[(size_t)n * 8 + h] + g_al[(size_t)n * 8 + 4 + h]);
        float4 hv = ldh4(g_h + (size_t)n * 128 + 4 * lane);
        z += e;
        acc.x += e * hv.x; acc.y += e * hv.y; acc.z += e * hv.z; acc.w += e * hv.w;
    }
    float inv = 1.f / z;
    float4 b = __ldg((const float4*)bias + lane);
    __half2 c0 = __floats2half2_rn(acc.x * inv + b.x, acc.y * inv + b.y);
    __half2 c1 = __floats2half2_rn(acc.z * inv + b.z, acc.w * inv + b.w);
    uint2 st;
    st.x = *(unsigned*)&c0;
    st.y = *(unsigned*)&c1;
    *(uint2*)(outh + (size_t)n * 128 + 4 * lane) = st;
}

template <int WPB>
__global__ __launch_bounds__(32 * WPB) void gat_mean_warp(
    const float* __restrict__ bias, float* __restrict__ out) {
    int wid = threadIdx.x >> 5, lane = threadIdx.x & 31;
    int n = blockIdx.x * WPB + wid;
    if (n >= NN) return;
    int h = lane >> 3;
    float ax = 0.f, ay = 0.f, z = 0.f;
    int k1 = g_row_end[n];
    int k = g_row_start[n];
    for (; k + 8 <= k1; k += 8) {
        int s[8];
        float e[8];
        float2 hv[8];
#pragma unroll
        for (int j = 0; j < 8; j++) {
            s[j] = g_adj[k + j] & 0xFFFF;
            e[j] = __ldg(g_ev + (size_t)(k + j) * 4 + h);
        }
#pragma unroll
        for (int j = 0; j < 8; j++) hv[j] = ldh2(g_h + (size_t)s[j] * 64 + 2 * lane);
#pragma unroll
        for (int j = 0; j < 8; j++) {
            z += e[j];
            ax += e[j] * hv[j].x;
            ay += e[j] * hv[j].y;
        }
    }
    for (; k + 4 <= k1; k += 4) {
        int s0 = g_adj[k + 0] & 0xFFFF, s1 = g_adj[k + 1] & 0xFFFF;
        int s2 = g_adj[k + 2] & 0xFFFF, s3 = g_adj[k + 3] & 0xFFFF;
        float e0 = __ldg(g_ev + (size_t)(k + 0) * 4 + h);
        float e1 = __ldg(g_ev + (size_t)(k + 1) * 4 + h);
        float e2 = __ldg(g_ev + (size_t)(k + 2) * 4 + h);
        float e3 = __ldg(g_ev + (size_t)(k + 3) * 4 + h);
        float2 h0 = ldh2(g_h + (size_t)s0 * 64 + 2 * lane);
        float2 h1 = ldh2(g_h + (size_t)s1 * 64 + 2 * lane);
        float2 h2 = ldh2(g_h + (size_t)s2 * 64 + 2 * lane);
        float2 h3 = ldh2(g_h + (size_t)s3 * 64 + 2 * lane);
        z += (e0 + e1) + (e2 + e3);
        ax += e0 * h0.x + e1 * h1.x + e2 * h2.x + e3 * h3.x;
        ay += e0 * h0.y + e1 * h1.y + e2 * h2.y + e3 * h3.y;
    }
    for (; k < k1; k++) {
        int s = g_adj[k] & 0xFFFF;
        float e = __ldg(g_ev + (size_t)k * 4 + h);
        float2 hv = ldh2(g_h + (size_t)s * 64 + 2 * lane);
        z += e;
        ax += e * hv.x;
        ay += e * hv.y;
    }
    {   // self loop
        float e = lrexp(g_al[(size_t)n * 8 + h] + g_al[(size_t)n * 8 + 4 + h]);
        float2 hv = ldh2(g_h + (size_t)n * 64 + 2 * lane);
        z += e;
        ax += e * hv.x;
        ay += e * hv.y;
    }
    float inv = 1.f / z;
    float vx = ax * inv, vy = ay * inv;
    vx += __shfl_xor_sync(0xffffffffu, vx, 8);
    vy += __shfl_xor_sync(0xffffffffu, vy, 8);
    vx += __shfl_xor_sync(0xffffffffu, vx, 16);
    vy += __shfl_xor_sync(0xffffffffu, vy, 16);
    if (lane < 8) {
        int c = 2 * lane;
        float sx = vx * 0.25f + __ldg(bias + c);
        float sy = vy * 0.25f + __ldg(bias + c + 1);
        sx = fmaxf(sx, 0.f);
        sy = fmaxf(sy, 0.f);
        float2 o;
        o.x = tanhf(sx);
        o.y = tanhf(sy);
        *(float2*)(out + (size_t)n * 16 + c) = o;
    }
}

// ---------------- launch ----------------
extern "C" void kernel_launch(void* const* d_in, const int* in_sizes, int n_in,
                              void* d_out, int out_size) {
    const float* x      = (const float*)d_in[0];
    const int*   ei     = (const int*)d_in[1];
    const int*   et     = (const int*)d_in[2];
    const float* basis1 = (const float*)d_in[3];
    const float* comp1  = (const float*)d_in[4];
    const float* root1  = (const float*)d_in[5];
    const float* brg1   = (const float*)d_in[6];
    const float* wg1    = (const float*)d_in[7];
    const float* asrc1  = (const float*)d_in[8];
    const float* adst1  = (const float*)d_in[9];
    const float* bg1    = (const float*)d_in[10];
    const float* basis2 = (const float*)d_in[11];
    const float* comp2  = (const float*)d_in[12];
    const float* root2  = (const float*)d_in[13];
    const float* brg2   = (const float*)d_in[14];
    const float* wg2    = (const float*)d_in[15];
    const float* asrc2  = (const float*)d_in[16];
    const float* adst2  = (const float*)d_in[17];
    const float* bg2    = (const float*)d_in[18];
    float* out = (float*)d_out;
    const int* src = ei;
    const int* dst = ei + EE;

    __half *p_xh, *p_x1h, *p_x2h, *p_x3h, *p_h, *p_w1h, *p_wg1h, *p_w2h, *p_wg2h, *p_z;
    cudaGetSymbolAddress((void**)&p_z, g_z);
    cudaGetSymbolAddress((void**)&p_xh, g_xh);
    cudaGetSymbolAddress((void**)&p_x1h, g_x1h);
    cudaGetSymbolAddress((void**)&p_x2h, g_x2h);
    cudaGetSymbolAddress((void**)&p_x3h, g_x3h);
    cudaGetSymbolAddress((void**)&p_h, g_h);
    cudaGetSymbolAddress((void**)&p_w1h, g_w1h);
    cudaGetSymbolAddress((void**)&p_wg1h, g_wg1h);
    cudaGetSymbolAddress((void**)&p_w2h, g_w2h);
    cudaGetSymbolAddress((void**)&p_wg2h, g_wg2h);

    // --- CSR build + one-time fp16 conversions ---
    zero_cnt<<<(NN * RR + 255) / 256, 256>>>();
    hist_kernel<<<(EE + 255) / 256, 256>>>(dst, et);
    scan_fused<<<NB, 256>>>();
    fill_kernel<<<(EE + 255) / 256, 256>>>(src, dst, et);
    conv_kernel<<<(NN * 16 + 255) / 256, 256>>>(x, basis1, root1, wg1, basis2, root2, wg2);

    const int WPB = 4;
    int nblk = (NN + WPB - 1) / WPB;

    // ---- RGCN 1: 64 -> 64, relu (fp16 out) ----
    rgcn_gather_z<64, WPB, 8><<<nblk, 32 * WPB>>>(p_xh, comp1);
    tgemm<256, 64, 64, 1, 0, 32><<<(NN + 63) / 64, 128>>>(
        p_z, p_xh, p_w1h, brg1, p_x1h, nullptr, nullptr);
    // ---- GAT 1: 64 -> 4x32 concat ----
    tgemm<64, 0, 128, 2, 1, 32><<<(NN + 31) / 32, 128>>>(
        p_x1h, nullptr, p_wg1h, nullptr, p_h, asrc1, adst1);
    ev_kernel<<<(EE + 255) / 256, 256>>>(src, dst);
    gat_concat_warp<WPB><<<nblk, 32 * WPB>>>(bg1, p_x2h);
    // ---- RGCN 2: 128 -> 32, relu (fp16 out) ----
    rgcn_gather_z<128, WPB, 4><<<nblk, 32 * WPB>>>(p_x2h, comp2);
    tgemm<512, 128, 32, 1, 0, 32><<<(NN + 63) / 64, 128>>>(
        p_z, p_x2h, p_w2h, brg2, p_x3h, nullptr, nullptr);
    // ---- GAT 2: 32 -> 4x16, mean heads, relu, tanh ----
    tgemm<32, 0, 64, 1, 1, 16><<<(NN + 63) / 64, 128>>>(
        p_x3h, nullptr, p_wg2h, nullptr, p_h, asrc2, adst2);
    ev_kernel<<<(EE + 255) / 256, 256>>>(src, dst);
    gat_mean_warp<WPB><<<nblk, 32 * WPB>>>(bg2, out);
}

// round 17
// speedup vs baseline: 1.0974x; 1.0478x over previous
#include <cuda_runtime.h>
#include <cuda_fp16.h>
#include <math.h>

#define NN 50000
#define EE 800000
#define RR 8
#define BB 4
#define NB ((NN + 255) / 256)

// ---------------- scratch (device globals; no allocation) ----------------
__device__ __half g_xh[NN * 64];        // fp16 input x
__device__ __half g_x1h[NN * 64];       // after RGCN1 (fp16)
__device__ __half g_x2h[NN * 128];      // after GAT1 (fp16)
__device__ __half g_x3h[NN * 32];       // after RGCN2 (fp16)
__device__ __half g_h[NN * 128];        // GAT transformed features (fp16)
__device__ float  g_al[NN * 8];
__device__ __half g_z[(size_t)NN * 512];  // B-space aggregates (fp16)
__device__ int    g_cnt[NN * RR];
__device__ int    g_row_start[NN];
__device__ int    g_row_end[NN];
__device__ int    g_cursor[NN];
__device__ int    g_grand;
__device__ int    g_adj[EE];            // src | (etype<<16)
__device__ __half g_w1h[320 * 64];
__device__ __half g_wg1h[64 * 128];
__device__ __half g_w2h[640 * 32];
__device__ __half g_wg2h[32 * 64];

__device__ __forceinline__ float4 ld4(const float* p) { return __ldg((const float4*)p); }
__device__ __forceinline__ float2 ld2(const float* p) { return __ldg((const float2*)p); }

__device__ __forceinline__ float4 ldh4(const __half* p) {
    uint2 raw = __ldg((const uint2*)p);
    __half2 a = *(__half2*)&raw.x;
    __half2 b = *(__half2*)&raw.y;
    float2 fa = __half22float2(a), fb = __half22float2(b);
    return make_float4(fa.x, fa.y, fb.x, fb.y);
}
__device__ __forceinline__ float2 ldh2(const __half* p) {
    __half2 h = __ldg((const __half2*)p);
    return __half22float2(h);
}

template <int VW>
__device__ __forceinline__ void ldvh(float (&d)[VW], const __half* p) {
    if (VW == 2) {
        float2 v = ldh2(p);
        d[0] = v.x; d[1] = v.y;
    } else {
        float4 v = ldh4(p);
        d[0] = v.x; d[1] = v.y; d[2] = v.z; d[3] = v.w;
    }
}

// ---------------- tensor-core primitives ----------------
__device__ __forceinline__ void ldsm4(unsigned& r0, unsigned& r1, unsigned& r2, unsigned& r3,
                                      unsigned addr) {
    asm volatile("ldmatrix.sync.aligned.m8n8.x4.shared.b16 {%0,%1,%2,%3}, [%4];"
                 : "=r"(r0), "=r"(r1), "=r"(r2), "=r"(r3) : "r"(addr));
}
__device__ __forceinline__ void ldsm4t(unsigned& r0, unsigned& r1, unsigned& r2, unsigned& r3,
                                       unsigned addr) {
    asm volatile("ldmatrix.sync.aligned.m8n8.x4.trans.shared.b16 {%0,%1,%2,%3}, [%4];"
                 : "=r"(r0), "=r"(r1), "=r"(r2), "=r"(r3) : "r"(addr));
}
__device__ __forceinline__ void mma16816(float* d, unsigned a0, unsigned a1, unsigned a2, unsigned a3,
                                         unsigned b0, unsigned b1) {
    asm volatile("mma.sync.aligned.m16n8k16.row.col.f32.f16.f16.f32 "
                 "{%0,%1,%2,%3},{%4,%5,%6,%7},{%8,%9},{%0,%1,%2,%3};"
                 : "+f"(d[0]), "+f"(d[1]), "+f"(d[2]), "+f"(d[3])
                 : "r"(a0), "r"(a1), "r"(a2), "r"(a3), "r"(b0), "r"(b1));
}

// ---------------- CSR build ----------------
__global__ void zero_cnt() {
    int i = blockIdx.x * blockDim.x + threadIdx.x;
    if (i < NN * RR) g_cnt[i] = 0;
    if (i == 0) g_grand = 0;
}

__global__ void hist_kernel(const int* __restrict__ dst, const int* __restrict__ et) {
    int e = blockIdx.x * blockDim.x + threadIdx.x;
    if (e < EE) atomicAdd(&g_cnt[dst[e] * RR + et[e]], 1);
}

__global__ void scan_fused() {
    __shared__ int sh[256];
    __shared__ int base_sh;
    int t = threadIdx.x;
    int n = blockIdx.x * 256 + t;
    int deg = 0;
    if (n < NN) {
#pragma unroll
        for (int r = 0; r < RR; r++) deg += g_cnt[n * RR + r];
    }
    int val = deg;
    sh[t] = val;
    __syncthreads();
    for (int d = 1; d < 256; d <<= 1) {
        int a = (t >= d) ? sh[t - d] : 0;
        __syncthreads();
        val += a;
        sh[t] = val;
        __syncthreads();
    }
    if (t == 255) base_sh = atomicAdd(&g_grand, val);
    __syncthreads();
    if (n < NN) {
        int start = base_sh + val - deg;
        g_row_start[n] = start;
        g_row_end[n] = start + deg;
        g_cursor[n] = start;
    }
}

__global__ void fill_kernel(const int* __restrict__ src, const int* __restrict__ dst,
                            const int* __restrict__ et) {
    int e = blockIdx.x * blockDim.x + threadIdx.x;
    if (e < EE) {
        int d = dst[e];
        int pos = atomicAdd(&g_cursor[d], 1);
        g_adj[pos] = src[e] | (et[e] << 16);
    }
}

// ---------------- fp16 conversions (once per launch, fused) ----------------
__global__ void conv_kernel(const float* __restrict__ x,
                            const float* __restrict__ b1, const float* __restrict__ r1,
                            const float* __restrict__ w1, const float* __restrict__ b2,
                            const float* __restrict__ r2, const float* __restrict__ w2) {
    int i = blockIdx.x * blockDim.x + threadIdx.x;
    if (i < NN * 64 / 4) {
        float4 v = ld4(x + 4 * i);
        __half2 h0 = __floats2half2_rn(v.x, v.y);
        __half2 h1 = __floats2half2_rn(v.z, v.w);
        uint2 st;
        st.x = *(unsigned*)&h0;
        st.y = *(unsigned*)&h1;
        *(uint2*)(g_xh + 4 * i) = st;
    }
    if (i < 16384)      g_w1h[i] = __float2half(b1[i]);
    else if (i < 20480) g_w1h[i] = __float2half(r1[i - 16384]);
    else if (i < 28672) g_wg1h[i - 20480] = __float2half(w1[i - 20480]);
    else if (i < 45056) g_w2h[i - 28672] = __float2half(b2[i - 28672]);
    else if (i < 49152) g_w2h[i - 28672] = __float2half(r2[i - 45056]);
    else if (i < 51200) g_wg2h[i - 49152] = __float2half(w2[i - 49152]);
}

// ---------------- RGCN: warp-per-node gather (fp16 rows) -> z[n, BB*IN] (fp16) ----------------
template <int IN, int WPB, int UN>
__global__ __launch_bounds__(32 * WPB) void rgcn_gather_z(
    const __half* __restrict__ x, const float* __restrict__ comp) {
    const int VW = IN / 32;
    __shared__ float wsh[WPB][RR * BB];
    int wid = threadIdx.x >> 5, lane = threadIdx.x & 31;
    int n = blockIdx.x * WPB + wid;
    if (n >= NN) return;

    if (lane < RR) {
        float ic = 1.f / fmaxf((float)g_cnt[n * RR + lane], 1.f);
#pragma unroll
        for (int b = 0; b < BB; b++) wsh[wid][lane * BB + b] = comp[lane * BB + b] * ic;
    }
    __syncwarp();

    float acc[BB][VW];
#pragma unroll
    for (int b = 0; b < BB; b++)
#pragma unroll
        for (int c = 0; c < VW; c++) acc[b][c] = 0.f;

    int k1 = g_row_end[n];
    int k = g_row_start[n];
    if (UN == 8) {
        for (; k + 8 <= k1; k += 8) {
            int v[8];
            float xr[8][VW];
#pragma unroll
            for (int j = 0; j < 8; j++) {
                v[j] = g_adj[k + j];
                ldvh<VW>(xr[j], x + (size_t)(v[j] & 0xFFFF) * IN + VW * lane);
            }
#pragma unroll
            for (int j = 0; j < 8; j++) {
                const float* w = &wsh[wid][(v[j] >> 16) * BB];
#pragma unroll
                for (int b = 0; b < BB; b++)
#pragma unroll
                    for (int c = 0; c < VW; c++) acc[b][c] += w[b] * xr[j][c];
            }
        }
    }
    for (; k + 4 <= k1; k += 4) {
        int v[4];
        float xr[4][VW];
#pragma unroll
        for (int j = 0; j < 4; j++) {
            v[j] = g_adj[k + j];
            ldvh<VW>(xr[j], x + (size_t)(v[j] & 0xFFFF) * IN + VW * lane);
        }
#pragma unroll
        for (int j = 0; j < 4; j++) {
            const float* w = &wsh[wid][(v[j] >> 16) * BB];
#pragma unroll
            for (int b = 0; b < BB; b++)
#pragma unroll
                for (int c = 0; c < VW; c++) acc[b][c] += w[b] * xr[j][c];
        }
    }
    for (; k < k1; k++) {
        int v = g_adj[k];
        float xr[VW];
        ldvh<VW>(xr, x + (size_t)(v & 0xFFFF) * IN + VW * lane);
        const float* w = &wsh[wid][(v >> 16) * BB];
#pragma unroll
        for (int b = 0; b < BB; b++)
#pragma unroll
            for (int c = 0; c < VW; c++) acc[b][c] += w[b] * xr[c];
    }
    __half* zp = g_z + (size_t)n * (BB * IN);
#pragma unroll
    for (int b = 0; b < BB; b++) {
        if (VW == 2) {
            __half2 o = __floats2half2_rn(acc[b][0], acc[b][1]);
            *(__half2*)(zp + b * IN + 2 * lane) = o;
        } else {
            __half2 o0 = __floats2half2_rn(acc[b][0], acc[b][1]);
            __half2 o1 = __floats2half2_rn(acc[b][VW - 2], acc[b][VW - 1]);
            uint2 st;
            st.x = *(unsigned*)&o0;
            st.y = *(unsigned*)&o1;
            *(uint2*)(zp + b * IN + 4 * lane) = st;
        }
    }
}

// ---------------- tensor-core GEMM (all-fp16 I/O) ----------------
template <int K1, int K2, int N, int WSPLIT, int MODE, int CH>
__global__ __launch_bounds__(128) void tgemm(
    const __half* __restrict__ A1, const __half* __restrict__ A2,
    const __half* __restrict__ W, const float* __restrict__ bias,
    __half* __restrict__ Hout,
    const float* __restrict__ asrc, const float* __restrict__ adst) {
    const int MT = 64 / WSPLIT;
    const int LDA = 40;
    const int LDB = N + 8;
    const int NW = N / (8 * WSPLIT);
    __shared__ __half At[MT * LDA];
    __shared__ __half Wt[32 * LDB];
    int tid = threadIdx.x;
    int wid = tid >> 5, lane = tid & 31;
    int warp_m = wid / WSPLIT, warp_n = wid % WSPLIT;
    int colbase = warp_n * (N / WSPLIT);
    int m0 = blockIdx.x * MT;

    float acc[NW][4];
#pragma unroll
    for (int i = 0; i < NW; i++)
#pragma unroll
        for (int j = 0; j < 4; j++) acc[i][j] = 0.f;

    unsigned sA = (unsigned)__cvta_generic_to_shared(At);
    unsigned sB = (unsigned)__cvta_generic_to_shared(Wt);

    const int T1 = K1 / 32, T2 = K2 / 32;
    for (int t = 0; t < T1 + T2; t++) {
        const __half* A;
        int ks, kstride;
        if (t < T1) { A = A1; ks = t * 32; kstride = K1; }
        else        { A = A2; ks = (t - T1) * 32; kstride = K2; }
        int wks = t * 32;
        __syncthreads();
        for (int idx = tid; idx < MT * 8; idx += 128) {
            int m = idx >> 3, q = idx & 7;
            int gm = m0 + m; if (gm >= NN) gm = NN - 1;
            uint2 v = __ldg((const uint2*)(A + (size_t)gm * kstride + ks + 4 * q));
            *(uint2*)&At[m * LDA + 4 * q] = v;
        }
        for (int idx = tid; idx < 32 * N / 4; idx += 128) {
            int row = idx / (N / 4), cq = idx % (N / 4);
            uint2 v = __ldg((const uint2*)(W + (size_t)(wks + row) * N + 4 * cq));
            *(uint2*)&Wt[row * LDB + 4 * cq] = v;
        }
        __syncthreads();
#pragma unroll
        for (int k16 = 0; k16 < 2; k16++) {
            unsigned a0, a1, a2, a3;
            unsigned aaddr = sA + ((warp_m * 16 + (lane & 15)) * LDA + k16 * 16 + (lane >> 4) * 8) * 2;
            ldsm4(a0, a1, a2, a3, aaddr);
#pragma unroll
            for (int tp = 0; tp < NW / 2; tp++) {
                int n0 = colbase + tp * 16;
                unsigned b0, b1, b2, b3;
                unsigned baddr = sB + ((k16 * 16 + (lane & 15)) * LDB + n0 + (lane >> 4) * 8) * 2;
                ldsm4t(b0, b1, b2, b3, baddr);
                mma16816(acc[2 * tp], a0, a1, a2, a3, b0, b1);
                mma16816(acc[2 * tp + 1], a0, a1, a2, a3, b2, b3);
            }
        }
    }
    // epilogue
    int r0 = m0 + warp_m * 16 + (lane >> 2);
    int r1 = r0 + 8;
    if (MODE == 0) {
#pragma unroll
        for (int tn = 0; tn < NW; tn++) {
            int c = colbase + 8 * tn + 2 * (lane & 3);
            float2 bv = ld2(bias + c);
            if (r0 < NN) {
                __half2 o = __floats2half2_rn(fmaxf(acc[tn][0] + bv.x, 0.f),
                                              fmaxf(acc[tn][1] + bv.y, 0.f));
                *(__half2*)(Hout + (size_t)r0 * N + c) = o;
            }
            if (r1 < NN) {
                __half2 o = __floats2half2_rn(fmaxf(acc[tn][2] + bv.x, 0.f),
                                              fmaxf(acc[tn][3] + bv.y, 0.f));
                *(__half2*)(Hout + (size_t)r1 * N + c) = o;
            }
        }
    } else {
        const int NH = N / (WSPLIT * CH);  // heads per warp
        float ps0[NH], pd0[NH], ps1[NH], pd1[NH];
#pragma unroll
        for (int i = 0; i < NH; i++) { ps0[i] = pd0[i] = ps1[i] = pd1[i] = 0.f; }
#pragma unroll
        for (int tn = 0; tn < NW; tn++) {
            int c = colbase + 8 * tn + 2 * (lane & 3);
            if (r0 < NN) {
                __half2 o = __floats2half2_rn(acc[tn][0], acc[tn][1]);
                *(__half2*)(Hout + (size_t)r0 * N + c) = o;
            }
            if (r1 < NN) {
                __half2 o = __floats2half2_rn(acc[tn][2], acc[tn][3]);
                *(__half2*)(Hout + (size_t)r1 * N + c) = o;
            }
            float2 a = ld2(asrc + c);
            float2 d = ld2(adst + c);
            int hl = (8 * tn) / CH;
            ps0[hl] += acc[tn][0] * a.x + acc[tn][1] * a.y;
            pd0[hl] += acc[tn][0] * d.x + acc[tn][1] * d.y;
            ps1[hl] += acc[tn][2] * a.x + acc[tn][3] * a.y;
            pd1[hl] += acc[tn][2] * d.x + acc[tn][3] * d.y;
        }
#pragma unroll
        for (int hl = 0; hl < NH; hl++) {
            float a0 = ps0[hl], b0 = pd0[hl], a1 = ps1[hl], b1 = pd1[hl];
            a0 += __shfl_xor_sync(0xffffffffu, a0, 1);
            b0 += __shfl_xor_sync(0xffffffffu, b0, 1);
            a1 += __shfl_xor_sync(0xffffffffu, a1, 1);
            b1 += __shfl_xor_sync(0xffffffffu, b1, 1);
            a0 += __shfl_xor_sync(0xffffffffu, a0, 2);
            b0 += __shfl_xor_sync(0xffffffffu, b0, 2);
            a1 += __shfl_xor_sync(0xffffffffu, a1, 2);
            b1 += __shfl_xor_sync(0xffffffffu, b1, 2);
            if ((lane & 3) == 0) {
                int hg = colbase / CH + hl;
                if (r0 < NN) {
                    g_al[(size_t)r0 * 8 + hg] = a0;
                    g_al[(size_t)r0 * 8 + 4 + hg] = b0;
                }
                if (r1 < NN) {
                    g_al[(size_t)r1 * 8 + hg] = a1;
                    g_al[(size_t)r1 * 8 + 4 + hg] = b1;
                }
            }
        }
    }
}

// ---------------- softmax numerator helper ----------------
__device__ __forceinline__ float lrexp(float v) {
    v = v > 0.f ? v : 0.2f * v;
    return __expf(v);
}

// ---------------- GAT gather: warp-per-node, sync-free, inline ev ----------------
template <int WPB>
__global__ __launch_bounds__(32 * WPB) void gat_concat_warp(
    const float* __restrict__ bias, __half* __restrict__ outh) {
    int wid = threadIdx.x >> 5, lane = threadIdx.x & 31;
    int n = blockIdx.x * WPB + wid;
    if (n >= NN) return;
    int h = lane >> 3;
    float aldst = g_al[(size_t)n * 8 + 4 + h];
    float4 acc = make_float4(0.f, 0.f, 0.f, 0.f);
    float z = 0.f;
    int k1 = g_row_end[n];
    int k = g_row_start[n];
    for (; k + 8 <= k1; k += 8) {
        int s[8];
        float av[8];
        float4 hv[8];
#pragma unroll
        for (int j = 0; j < 8; j++) {
            s[j] = g_adj[k + j] & 0xFFFF;
            av[j] = __ldg(g_al + (size_t)s[j] * 8 + h);
        }
#pragma unroll
        for (int j = 0; j < 8; j++) hv[j] = ldh4(g_h + (size_t)s[j] * 128 + 4 * lane);
#pragma unroll
        for (int j = 0; j < 8; j++) {
            float e = lrexp(av[j] + aldst);
            z += e;
            acc.x += e * hv[j].x;
            acc.y += e * hv[j].y;
            acc.z += e * hv[j].z;
            acc.w += e * hv[j].w;
        }
    }
    for (; k + 4 <= k1; k += 4) {
        int s[4];
        float av[4];
        float4 hv[4];
#pragma unroll
        for (int j = 0; j < 4; j++) {
            s[j] = g_adj[k + j] & 0xFFFF;
            av[j] = __ldg(g_al + (size_t)s[j] * 8 + h);
        }
#pragma unroll
        for (int j = 0; j < 4; j++) hv[j] = ldh4(g_h + (size_t)s[j] * 128 + 4 * lane);
#pragma unroll
        for (int j = 0; j < 4; j++) {
            float e = lrexp(av[j] + aldst);
            z += e;
            acc.x += e * hv[j].x;
            acc.y += e * hv[j].y;
            acc.z += e * hv[j].z;
            acc.w += e * hv[j].w;
        }
    }
    for (; k < k1; k++) {
        int s = g_adj[k] & 0xFFFF;
        float e = lrexp(__ldg(g_al + (size_t)s * 8 + h) + aldst);
        float4 hv = ldh4(g_h + (size_t)s * 128 + 4 * lane);
        z += e;
        acc.x += e * hv.x; acc.y += e * hv.y; acc.z += e * hv.z; acc.w += e * hv.w;
    }
    {   // self loop
        float e = lrexp(g_al[(size_t)n * 8 + h] + aldst);
        float4 hv = ldh4(g_h + (size_t)n * 128 + 4 * lane);
        z += e;
        acc.x += e * hv.x; acc.y += e * hv.y; acc.z += e * hv.z; acc.w += e * hv.w;
    }
    float inv = 1.f / z;
    float4 b = __ldg((const float4*)bias + lane);
    __half2 c0 = __floats2half2_rn(acc.x * inv + b.x, acc.y * inv + b.y);
    __half2 c1 = __floats2half2_rn(acc.z * inv + b.z, acc.w * inv + b.w);
    uint2 st;
    st.x = *(unsigned*)&c0;
    st.y = *(unsigned*)&c1;
    *(uint2*)(outh + (size_t)n * 128 + 4 * lane) = st;
}

template <int WPB>
__global__ __launch_bounds__(32 * WPB) void gat_mean_warp(
    const float* __restrict__ bias, float* __restrict__ out) {
    int wid = threadIdx.x >> 5, lane = threadIdx.x & 31;
    int n = blockIdx.x * WPB + wid;
    if (n >= NN) return;
    int h = lane >> 3;
    float aldst = g_al[(size_t)n * 8 + 4 + h];
    float ax = 0.f, ay = 0.f, z = 0.f;
    int k1 = g_row_end[n];
    int k = g_row_start[n];
    for (; k + 8 <= k1; k += 8) {
        int s[8];
        float av[8];
        float2 hv[8];
#pragma unroll
        for (int j = 0; j < 8; j++) {
            s[j] = g_adj[k + j] & 0xFFFF;
            av[j] = __ldg(g_al + (size_t)s[j] * 8 + h);
        }
#pragma unroll
        for (int j = 0; j < 8; j++) hv[j] = ldh2(g_h + (size_t)s[j] * 64 + 2 * lane);
#pragma unroll
        for (int j = 0; j < 8; j++) {
            float e = lrexp(av[j] + aldst);
            z += e;
            ax += e * hv[j].x;
            ay += e * hv[j].y;
        }
    }
    for (; k + 4 <= k1; k += 4) {
        int s[4];
        float av[4];
        float2 hv[4];
#pragma unroll
        for (int j = 0; j < 4; j++) {
            s[j] = g_adj[k + j] & 0xFFFF;
            av[j] = __ldg(g_al + (size_t)s[j] * 8 + h);
        }
#pragma unroll
        for (int j = 0; j < 4; j++) hv[j] = ldh2(g_h + (size_t)s[j] * 64 + 2 * lane);
#pragma unroll
        for (int j = 0; j < 4; j++) {
            float e = lrexp(av[j] + aldst);
            z += e;
            ax += e * hv[j].x;
            ay += e * hv[j].y;
        }
    }
    for (; k < k1; k++) {
        int s = g_adj[k] & 0xFFFF;
        float e = lrexp(__ldg(g_al + (size_t)s * 8 + h) + aldst);
        float2 hv = ldh2(g_h + (size_t)s * 64 + 2 * lane);
        z += e;
        ax += e * hv.x;
        ay += e * hv.y;
    }
    {   // self loop
        float e = lrexp(g_al[(size_t)n * 8 + h] + aldst);
        float2 hv = ldh2(g_h + (size_t)n * 64 + 2 * lane);
        z += e;
        ax += e * hv.x;
        ay += e * hv.y;
    }
    float inv = 1.f / z;
    float vx = ax * inv, vy = ay * inv;
    vx += __shfl_xor_sync(0xffffffffu, vx, 8);
    vy += __shfl_xor_sync(0xffffffffu, vy, 8);
    vx += __shfl_xor_sync(0xffffffffu, vx, 16);
    vy += __shfl_xor_sync(0xffffffffu, vy, 16);
    if (lane < 8) {
        int c = 2 * lane;
        float sx = vx * 0.25f + __ldg(bias + c);
        float sy = vy * 0.25f + __ldg(bias + c + 1);
        sx = fmaxf(sx, 0.f);
        sy = fmaxf(sy, 0.f);
        float2 o;
        o.x = tanhf(sx);
        o.y = tanhf(sy);
        *(float2*)(out + (size_t)n * 16 + c) = o;
    }
}

// ---------------- launch ----------------
extern "C" void kernel_launch(void* const* d_in, const int* in_sizes, int n_in,
                              void* d_out, int out_size) {
    const float* x      = (const float*)d_in[0];
    const int*   ei     = (const int*)d_in[1];
    const int*   et     = (const int*)d_in[2];
    const float* basis1 = (const float*)d_in[3];
    const float* comp1  = (const float*)d_in[4];
    const float* root1  = (const float*)d_in[5];
    const float* brg1   = (const float*)d_in[6];
    const float* wg1    = (const float*)d_in[7];
    const float* asrc1  = (const float*)d_in[8];
    const float* adst1  = (const float*)d_in[9];
    const float* bg1    = (const float*)d_in[10];
    const float* basis2 = (const float*)d_in[11];
    const float* comp2  = (const float*)d_in[12];
    const float* root2  = (const float*)d_in[13];
    const float* brg2   = (const float*)d_in[14];
    const float* wg2    = (const float*)d_in[15];
    const float* asrc2  = (const float*)d_in[16];
    const float* adst2  = (const float*)d_in[17];
    const float* bg2    = (const float*)d_in[18];
    float* out = (float*)d_out;
    const int* src = ei;
    const int* dst = ei + EE;

    __half *p_xh, *p_x1h, *p_x2h, *p_x3h, *p_h, *p_w1h, *p_wg1h, *p_w2h, *p_wg2h, *p_z;
    cudaGetSymbolAddress((void**)&p_z, g_z);
    cudaGetSymbolAddress((void**)&p_xh, g_xh);
    cudaGetSymbolAddress((void**)&p_x1h, g_x1h);
    cudaGetSymbolAddress((void**)&p_x2h, g_x2h);
    cudaGetSymbolAddress((void**)&p_x3h, g_x3h);
    cudaGetSymbolAddress((void**)&p_h, g_h);
    cudaGetSymbolAddress((void**)&p_w1h, g_w1h);
    cudaGetSymbolAddress((void**)&p_wg1h, g_wg1h);
    cudaGetSymbolAddress((void**)&p_w2h, g_w2h);
    cudaGetSymbolAddress((void**)&p_wg2h, g_wg2h);

    // --- CSR build + one-time fp16 conversions ---
    zero_cnt<<<(NN * RR + 255) / 256, 256>>>();
    hist_kernel<<<(EE + 255) / 256, 256>>>(dst, et);
    scan_fused<<<NB, 256>>>();
    fill_kernel<<<(EE + 255) / 256, 256>>>(src, dst, et);
    conv_kernel<<<(NN * 16 + 255) / 256, 256>>>(x, basis1, root1, wg1, basis2, root2, wg2);

    const int WPB = 4;
    int nblk = (NN + WPB - 1) / WPB;

    // ---- RGCN 1: 64 -> 64, relu (fp16 out) ----
    rgcn_gather_z<64, WPB, 8><<<nblk, 32 * WPB>>>(p_xh, comp1);
    tgemm<256, 64, 64, 1, 0, 32><<<(NN + 63) / 64, 128>>>(
        p_z, p_xh, p_w1h, brg1, p_x1h, nullptr, nullptr);
    // ---- GAT 1: 64 -> 4x32 concat ----
    tgemm<64, 0, 128, 2, 1, 32><<<(NN + 31) / 32, 128>>>(
        p_x1h, nullptr, p_wg1h, nullptr, p_h, asrc1, adst1);
    gat_concat_warp<WPB><<<nblk, 32 * WPB>>>(bg1, p_x2h);
    // ---- RGCN 2: 128 -> 32, relu (fp16 out) ----
    rgcn_gather_z<128, WPB, 4><<<nblk, 32 * WPB>>>(p_x2h, comp2);
    tgemm<512, 128, 32, 1, 0, 32><<<(NN + 63) / 64, 128>>>(
        p_z, p_x2h, p_w2h, brg2, p_x3h, nullptr, nullptr);
    // ---- GAT 2: 32 -> 4x16, mean heads, relu, tanh ----
    tgemm<32, 0, 64, 1, 1, 16><<<(NN + 63) / 64, 128>>>(
        p_x3h, nullptr, p_wg2h, nullptr, p_h, asrc2, adst2);
    gat_mean_warp<WPB><<<nblk, 32 * WPB>>>(bg2, out);
}